// round 16
// baseline (speedup 1.0000x reference)
#include <cuda_runtime.h>
#include <cuda_fp16.h>
#include <math.h>

#define NN 50000
#define EE 1280000
#define NBLK 196            // ceil(NN/256)
#define CAP 128             // smem-staged edges per node

// ---------------- device scratch ----------------
__device__ __align__(16) int    g_csr_src[EE];
__device__ __align__(16) float  g_csr_gate[EE];
__device__ __align__(16) float2 g_ec[EE + 8];       // fallback staging (deg > CAP only)
__device__ __align__(16) __half g_Hh[NN * 64];      // H = X@W   (fp16 for gather BW)
__device__ __align__(16) __half g_xh[NN * 64];      // xhat      (fp16 for gather BW)
__device__ __align__(16) float  g_h0[NN * 64];
__device__ __align__(16) float  g_xres[NN * 64];
__device__ __align__(16) float  g_ad[NN];
__device__ __align__(16) float  g_as[NN];
__device__ int g_cnt[NN];
__device__ int g_rowptr[NN + 1];
__device__ int g_cur[NN];
__device__ int g_scan_state[NBLK];   // 0=invalid 1=aggregate 2=inclusive-prefix
__device__ int g_scan_agg[NBLK];
__device__ int g_scan_inc[NBLK];
__device__ int g_is64;

__device__ __forceinline__ float elu1(float v) { return v > 0.f ? v : expm1f(v); }

// ---------------- init: zero counters + scan state, detect dtype ----------------
__global__ void init_kernel(const int* __restrict__ ei_words) {
    int i = blockIdx.x * blockDim.x + threadIdx.x;
    if (i < NN) g_cnt[i] = 0;
    if (i < NBLK) g_scan_state[i] = 0;
    if (blockIdx.x == 0 && threadIdx.x < 32) {
        int lane = threadIdx.x;
        int nonzero = 0;
#pragma unroll
        for (int it = 0; it < 32; it++) {
            int w = 1 + 2 * (lane + it * 32);        // odd words of first 2048
            nonzero |= (ei_words[w] != 0);
        }
        unsigned any = __ballot_sync(0xffffffffu, nonzero);
        if (lane == 0) g_is64 = (any == 0u);
    }
}

__device__ __forceinline__ int parse_dst(const int* ei, int e) {
    int d = g_is64 ? ei[2 * (EE + e)] : ei[EE + e];
    return min(max(d, 0), NN - 1);
}
__device__ __forceinline__ int parse_src(const int* ei, int e) {
    int s = g_is64 ? ei[2 * e] : ei[e];
    return min(max(s, 0), NN - 1);
}

// ---------------- histogram of dst ----------------
__global__ void edge_hist(const int* __restrict__ ei) {
    int e = blockIdx.x * blockDim.x + threadIdx.x;
    if (e >= EE) return;
    atomicAdd(&g_cnt[parse_dst(ei, e)], 1);
}

// ---------------- single-kernel decoupled-lookback exclusive scan ----------------
// All NBLK=196 blocks are co-resident (8 blocks/SM x 148 SMs >> 196): no deadlock.
__global__ void scan_lookback() {
    __shared__ int sm[256];
    __shared__ int s_prefix;
    int b = blockIdx.x, t = threadIdx.x;
    int i = b * 256 + t;
    int v = (i < NN) ? g_cnt[i] : 0;
    sm[t] = v; __syncthreads();
    int acc = v;
#pragma unroll
    for (int o = 1; o < 256; o <<= 1) {
        int add = (t >= o) ? sm[t - o] : 0;
        __syncthreads();
        acc += add; sm[t] = acc;
        __syncthreads();
    }
    int blockAgg = sm[255];
    if (t == 0) {
        volatile int* vstate = g_scan_state;
        volatile int* vagg   = g_scan_agg;
        volatile int* vinc   = g_scan_inc;
        if (b == 0) {
            vinc[0] = blockAgg;
            __threadfence();
            vstate[0] = 2;
            s_prefix = 0;
        } else {
            vagg[b] = blockAgg;
            __threadfence();
            vstate[b] = 1;
            int ex = 0, pb = b - 1;
            while (true) {
                int st;
                while ((st = vstate[pb]) == 0) { }
                if (st == 2) { ex += vinc[pb]; break; }
                ex += vagg[pb]; pb--;
            }
            vinc[b] = ex + blockAgg;
            __threadfence();
            vstate[b] = 2;
            s_prefix = ex;
        }
    }
    __syncthreads();
    int off = s_prefix;
    if (i < NN) {
        g_rowptr[i + 1] = off + acc;
        g_cur[i]        = off + acc - v;
    }
    if (i == 0) g_rowptr[0] = 0;
}

// ---------------- scatter edges into CSR ----------------
__global__ void scatter_edges(const int* __restrict__ ei, const float* __restrict__ w) {
    int e = blockIdx.x * blockDim.x + threadIdx.x;
    if (e >= EE) return;
    int d = parse_dst(ei, e);
    int pos = atomicAdd(&g_cur[d], 1);
    g_csr_src[pos] = parse_src(ei, e);
    float wc = fminf(w[e], 4.f);
    g_csr_gate[pos] = fminf(fmaxf(1.f - 0.25f * wc, 0.f), 1.f);
}

// ---------------- fused residual MLP: relu(x@rW1+rb1)@rW2+rb2 -> g_xres ----------------
__global__ void gemm_res_fused(const float* __restrict__ X, const float* __restrict__ W1,
                               const float* __restrict__ B1, const float* __restrict__ W2,
                               const float* __restrict__ B2) {
    int warp = (blockIdx.x * blockDim.x + threadIdx.x) >> 5;
    int r0 = warp * 4;
    if (r0 >= NN) return;
    int lane = threadIdx.x & 31;
    float2 xa[4], t[4];
    float a0[4] = {0,0,0,0}, a1[4] = {0,0,0,0};
#pragma unroll
    for (int r = 0; r < 4; r++) xa[r] = ((const float2*)(X + (size_t)(r0 + r) * 64))[lane];
#pragma unroll
    for (int k = 0; k < 64; k += 2) {
        float2 w0 = ((const float2*)(W1 + k * 64))[lane];
        float2 w1 = ((const float2*)(W1 + (k + 1) * 64))[lane];
#pragma unroll
        for (int r = 0; r < 4; r++) {
            float x0 = __shfl_sync(0xffffffffu, xa[r].x, k >> 1);
            float x1 = __shfl_sync(0xffffffffu, xa[r].y, k >> 1);
            a0[r] += x0 * w0.x + x1 * w1.x;
            a1[r] += x0 * w0.y + x1 * w1.y;
        }
    }
    float bb0 = B1[2 * lane], bb1 = B1[2 * lane + 1];
#pragma unroll
    for (int r = 0; r < 4; r++) {
        t[r].x = fmaxf(a0[r] + bb0, 0.f);
        t[r].y = fmaxf(a1[r] + bb1, 0.f);
        a0[r] = 0.f; a1[r] = 0.f;
    }
#pragma unroll
    for (int k = 0; k < 64; k += 2) {
        float2 w0 = ((const float2*)(W2 + k * 64))[lane];
        float2 w1 = ((const float2*)(W2 + (k + 1) * 64))[lane];
#pragma unroll
        for (int r = 0; r < 4; r++) {
            float x0 = __shfl_sync(0xffffffffu, t[r].x, k >> 1);
            float x1 = __shfl_sync(0xffffffffu, t[r].y, k >> 1);
            a0[r] += x0 * w0.x + x1 * w1.x;
            a1[r] += x0 * w0.y + x1 * w1.y;
        }
    }
    float c0 = B2[2 * lane], c1 = B2[2 * lane + 1];
#pragma unroll
    for (int r = 0; r < 4; r++)
        ((float2*)(g_xres + (size_t)(r0 + r) * 64))[lane] = make_float2(a0[r] + c0, a1[r] + c1);
}

// ---------------- node prep: H=X@W (fp16 out), ad/as, xhat (fp16 out) ----------------
template <int LAYER>
__global__ void node_prep(const float* __restrict__ Xin, const float* __restrict__ W,
                          const float* __restrict__ att) {
    int warp = (blockIdx.x * blockDim.x + threadIdx.x) >> 5;
    int r0 = warp * 4;
    if (r0 >= NN) return;
    int lane = threadIdx.x & 31;
    const float* X = (LAYER == 0) ? Xin : g_h0;
    float2 xa[4];
    float a0[4] = {0,0,0,0}, a1[4] = {0,0,0,0};
#pragma unroll
    for (int r = 0; r < 4; r++) xa[r] = ((const float2*)(X + (size_t)(r0 + r) * 64))[lane];
#pragma unroll
    for (int k = 0; k < 64; k += 2) {
        float2 w0 = ((const float2*)(W + k * 64))[lane];
        float2 w1 = ((const float2*)(W + (k + 1) * 64))[lane];
#pragma unroll
        for (int r = 0; r < 4; r++) {
            float x0 = __shfl_sync(0xffffffffu, xa[r].x, k >> 1);
            float x1 = __shfl_sync(0xffffffffu, xa[r].y, k >> 1);
            a0[r] += x0 * w0.x + x1 * w1.x;
            a1[r] += x0 * w0.y + x1 * w1.y;
        }
    }
    float at0 = att[2 * lane], at1 = att[2 * lane + 1];
    float at2 = att[64 + 2 * lane], at3 = att[65 + 2 * lane];
#pragma unroll
    for (int r = 0; r < 4; r++) {
        ((__half2*)(g_Hh + (size_t)(r0 + r) * 64))[lane] = __floats2half2_rn(a0[r], a1[r]);
        float pa = a0[r] * at0 + a1[r] * at1;
        float pb = a0[r] * at2 + a1[r] * at3;
        float pn = xa[r].x * xa[r].x + xa[r].y * xa[r].y;
#pragma unroll
        for (int o = 16; o; o >>= 1) {
            pa += __shfl_xor_sync(0xffffffffu, pa, o);
            pb += __shfl_xor_sync(0xffffffffu, pb, o);
            pn += __shfl_xor_sync(0xffffffffu, pn, o);
        }
        float inv = 1.f / fmaxf(sqrtf(pn), 1e-8f);
        ((__half2*)(g_xh + (size_t)(r0 + r) * 64))[lane] =
            __floats2half2_rn(xa[r].x * inv, xa[r].y * inv);
        if (lane == 0) { g_ad[r0 + r] = pa; g_as[r0 + r] = pb; }
    }
}

// unpack 8 halves (loaded as float4) to 8 floats
__device__ __forceinline__ void h8_to_f8(float4 raw, float* f) {
    const __half2* h = (const __half2*)&raw;
#pragma unroll
    for (int i = 0; i < 4; i++) {
        float2 v = __half22float2(h[i]);
        f[2 * i] = v.x; f[2 * i + 1] = v.y;
    }
}

// ---------------- fused edge engine: warp per node, smem staging ----------------
// 8 lanes/edge, 4 edges per warp-iteration. Per-edge (eg, ec, gate) staged in
// shared memory between the two passes (global g_ec fallback if deg > CAP).
template <int LAYER>
__global__ void edge_fused(const float* __restrict__ beta, const float* __restrict__ B,
                           float* __restrict__ outp) {
    __shared__ float sm_eg[8][CAP];
    __shared__ float sm_ec[8][CAP];
    __shared__ float sm_gt[8][CAP];
    int w = threadIdx.x >> 5;
    int n = (blockIdx.x * blockDim.x + threadIdx.x) >> 5;
    if (n >= NN) return;
    int lane = threadIdx.x & 31;
    int p = lane & 7;          // column-slot within 8-lane group (8 cols each)
    int grp = lane >> 3;       // edge group 0..3
    int esel = (lane * 8) & 31;

    float xq[8];
    h8_to_f8(((const float4*)(g_xh + (size_t)n * 64))[p], xq);
    float ad = g_ad[n];
    int beg = g_rowptr[n], end = g_rowptr[n + 1];
    int deg = end - beg;
    bool big = deg > CAP;
    float bb = 1.f / (1.f + __expf(-beta[0]));

    float sg = 0.f, sc = 0.f;

    // ---- pass A: dot + logit, raw exps, sums (pipelined) ----
    {
        int idx = beg + grp;
        int s = (idx < end) ? g_csr_src[idx] : 0;
        float4 raw = ((const float4*)(g_xh + (size_t)s * 64))[p];
        for (int j0 = beg; j0 < end; j0 += 4) {
            int idxn = j0 + 4 + grp;
            int sn = (idxn < end) ? g_csr_src[idxn] : 0;
            float4 rawn = ((const float4*)(g_xh + (size_t)sn * 64))[p];
            float q[8];
            h8_to_f8(raw, q);
            float d = 0.f;
#pragma unroll
            for (int i = 0; i < 8; i++) d += xq[i] * q[i];
            d += __shfl_xor_sync(0xffffffffu, d, 4, 8);
            d += __shfl_xor_sync(0xffffffffu, d, 2, 8);
            d += __shfl_xor_sync(0xffffffffu, d, 1, 8);
            float dsel = __shfl_sync(0xffffffffu, d, esel);
            int   ssel = __shfl_sync(0xffffffffu, s, esel);
            if (lane < min(4, end - j0)) {
                float lg = ad + g_as[ssel];
                lg = fmaxf(lg, 0.2f * lg);               // leaky relu
                float eg = __expf(lg);                   // no shift: |lg| small
                float ec = __expf(dsel);                 // cos in [-1,1]
                float gt = g_csr_gate[j0 + lane];
                if (!big) {
                    int jj = j0 - beg + lane;
                    sm_eg[w][jj] = eg; sm_ec[w][jj] = ec; sm_gt[w][jj] = gt;
                } else {
                    g_ec[j0 + lane] = make_float2(eg, ec);
                }
                sg += eg; sc += ec;
            }
            s = sn; raw = rawn;
        }
    }
    __syncwarp();
    sg += __shfl_xor_sync(0xffffffffu, sg, 1, 4);
    sg += __shfl_xor_sync(0xffffffffu, sg, 2, 4);
    sc += __shfl_xor_sync(0xffffffffu, sc, 1, 4);
    sc += __shfl_xor_sync(0xffffffffu, sc, 2, 4);
    sg = __shfl_sync(0xffffffffu, sg, 0);
    sc = __shfl_sync(0xffffffffu, sc, 0);
    float wg = (1.f - bb) / (sg + 1e-16f);
    float wc = bb / (sc + 1e-16f);

    // ---- pass C: fused alpha, gate, exp; unnormalized aggregate (pipelined) ----
    float acc[8] = {0,0,0,0,0,0,0,0};
    float st = 0.f;
    {
        int idx = beg + grp;
        int s = (idx < end) ? g_csr_src[idx] : 0;
        float4 hraw = ((const float4*)(g_Hh + (size_t)s * 64))[p];
        for (int j0 = beg; j0 < end; j0 += 4) {
            int idxn = j0 + 4 + grp;
            int sn = (idxn < end) ? g_csr_src[idxn] : 0;
            float4 hrawn = ((const float4*)(g_Hh + (size_t)sn * 64))[p];

            float et = 0.f;
            if (lane < min(4, end - j0)) {
                float eg, ec, gt;
                if (!big) {
                    int jj = j0 - beg + lane;
                    eg = sm_eg[w][jj]; ec = sm_ec[w][jj]; gt = sm_gt[w][jj];
                } else {
                    float2 le = g_ec[j0 + lane];
                    eg = le.x; ec = le.y; gt = g_csr_gate[j0 + lane];
                }
                float tv = (eg * wg + ec * wc) * gt;     // in [0,1]
                et = __expf(tv);
                st += et;
            }
            float etg = __shfl_sync(0xffffffffu, et, grp);
            float h[8];
            h8_to_f8(hraw, h);
#pragma unroll
            for (int i = 0; i < 8; i++) acc[i] += etg * h[i];

            s = sn; hraw = hrawn;
        }
    }
    st += __shfl_xor_sync(0xffffffffu, st, 1, 4);
    st += __shfl_xor_sync(0xffffffffu, st, 2, 4);
    st  = __shfl_sync(0xffffffffu, st, 0);
#pragma unroll
    for (int i = 0; i < 8; i++) {
        acc[i] += __shfl_xor_sync(0xffffffffu, acc[i], 8);
        acc[i] += __shfl_xor_sync(0xffffffffu, acc[i], 16);
    }
    float inv = 1.f / (st + 1e-16f);
    if (lane < 8) {                                  // grp==0 lanes hold final cols 8p..8p+8
        float o[8];
#pragma unroll
        for (int i = 0; i < 8; i++) o[i] = acc[i] * inv + B[p * 8 + i];
        if (LAYER == 0) {
#pragma unroll
            for (int i = 0; i < 8; i++) o[i] = elu1(elu1(o[i]));
            float4* dst = (float4*)(g_h0 + (size_t)n * 64 + p * 8);
            dst[0] = make_float4(o[0], o[1], o[2], o[3]);
            dst[1] = make_float4(o[4], o[5], o[6], o[7]);
        } else {
            const float4* rr = (const float4*)(g_xres + (size_t)n * 64 + p * 8);
            float4 r0 = rr[0], r1 = rr[1];
            o[0] = elu1(o[0]) + r0.x; o[1] = elu1(o[1]) + r0.y;
            o[2] = elu1(o[2]) + r0.z; o[3] = elu1(o[3]) + r0.w;
            o[4] = elu1(o[4]) + r1.x; o[5] = elu1(o[5]) + r1.y;
            o[6] = elu1(o[6]) + r1.z; o[7] = elu1(o[7]) + r1.w;
            float4* dst = (float4*)(outp + (size_t)n * 64 + p * 8);
            dst[0] = make_float4(o[0], o[1], o[2], o[3]);
            dst[1] = make_float4(o[4], o[5], o[6], o[7]);
        }
    }
}

// ---------------- launch ----------------
extern "C" void kernel_launch(void* const* d_in, const int* in_sizes, int n_in,
                              void* d_out, int out_size) {
    const float* x     = (const float*)d_in[0];
    const int*   ei    = (const int*)d_in[1];
    const float* ea    = (const float*)d_in[2];
    const float* W0    = (const float*)d_in[3];
    const float* att0  = (const float*)d_in[4];
    const float* beta0 = (const float*)d_in[5];
    const float* b0    = (const float*)d_in[6];
    const float* W1    = (const float*)d_in[7];
    const float* att1  = (const float*)d_in[8];
    const float* beta1 = (const float*)d_in[9];
    const float* b1    = (const float*)d_in[10];
    const float* rW1   = (const float*)d_in[11];
    const float* rb1   = (const float*)d_in[12];
    const float* rW2   = (const float*)d_in[13];
    const float* rb2   = (const float*)d_in[14];
    float* out = (float*)d_out;

    const int EDGE_GRID  = EE / 256;                 // 5000
    const int PREP_GRID  = (NN / 4 + 7) / 8;         // 1563 (4 rows/warp, 8 warps/blk)
    const int EDGEF_GRID = NN / 8;                   // 6250 (warp per node)

    init_kernel<<<NBLK, 256>>>(ei);                  // 0
    edge_hist<<<EDGE_GRID, 256>>>(ei);               // 1
    scan_lookback<<<NBLK, 256>>>();                  // 2
    scatter_edges<<<EDGE_GRID, 256>>>(ei, ea);       // 3

    node_prep<0><<<PREP_GRID, 256>>>(x, W0, att0);   // 4
    edge_fused<0><<<EDGEF_GRID, 256>>>(beta0, b0, out); // 5  <- ncu window

    node_prep<1><<<PREP_GRID, 256>>>(x, W1, att1);   // 6
    gemm_res_fused<<<PREP_GRID, 256>>>(x, rW1, rb1, rW2, rb2); // 7
    edge_fused<1><<<EDGEF_GRID, 256>>>(beta1, b1, out);        // 8
}

// round 17
// speedup vs baseline: 1.0473x; 1.0473x over previous
#include <cuda_runtime.h>
#include <cuda_fp16.h>
#include <math.h>

#define NN 50000
#define EE 1280000
#define NBLK 196            // ceil(NN/256)

// ---------------- device scratch ----------------
__device__ __align__(16) int2   g_csr[EE];          // {src, gate_bits} packed
__device__ __align__(16) float2 g_ec[EE + 8];       // (exp(logit), exp(cos)) per CSR edge
__device__ __align__(16) __half g_Hh[NN * 64];      // H = X@W   (fp16 for gather BW)
__device__ __align__(16) __half g_xh[NN * 64];      // xhat      (fp16 for gather BW)
__device__ __align__(16) float  g_h0[NN * 64];
__device__ __align__(16) float  g_xres[NN * 64];
__device__ __align__(16) float  g_ad[NN];
__device__ __align__(16) float  g_as[NN];
__device__ int g_cnt[NN];
__device__ int g_rowptr[NN + 1];
__device__ int g_cur[NN];
__device__ int g_scan_state[NBLK];   // 0=invalid 1=aggregate 2=inclusive-prefix
__device__ int g_scan_agg[NBLK];
__device__ int g_scan_inc[NBLK];
__device__ int g_is64;

__device__ __forceinline__ float elu1(float v) { return v > 0.f ? v : expm1f(v); }

// ---------------- init: zero counters + scan state, detect dtype ----------------
__global__ void init_kernel(const int* __restrict__ ei_words) {
    int i = blockIdx.x * blockDim.x + threadIdx.x;
    if (i < NN) g_cnt[i] = 0;
    if (i < NBLK) g_scan_state[i] = 0;
    if (blockIdx.x == 0 && threadIdx.x < 32) {
        int lane = threadIdx.x;
        int nonzero = 0;
#pragma unroll
        for (int it = 0; it < 32; it++) {
            int w = 1 + 2 * (lane + it * 32);        // odd words of first 2048
            nonzero |= (ei_words[w] != 0);
        }
        unsigned any = __ballot_sync(0xffffffffu, nonzero);
        if (lane == 0) g_is64 = (any == 0u);
    }
}

__device__ __forceinline__ int parse_dst(const int* ei, int e) {
    int d = g_is64 ? ei[2 * (EE + e)] : ei[EE + e];
    return min(max(d, 0), NN - 1);
}
__device__ __forceinline__ int parse_src(const int* ei, int e) {
    int s = g_is64 ? ei[2 * e] : ei[e];
    return min(max(s, 0), NN - 1);
}

// ---------------- histogram of dst ----------------
__global__ void edge_hist(const int* __restrict__ ei) {
    int e = blockIdx.x * blockDim.x + threadIdx.x;
    if (e >= EE) return;
    atomicAdd(&g_cnt[parse_dst(ei, e)], 1);
}

// ---------------- single-kernel decoupled-lookback exclusive scan ----------------
// All NBLK=196 blocks co-resident (196 < 148 SMs * many blocks): no deadlock.
__global__ void scan_lookback() {
    __shared__ int sm[256];
    __shared__ int s_prefix;
    int b = blockIdx.x, t = threadIdx.x;
    int i = b * 256 + t;
    int v = (i < NN) ? g_cnt[i] : 0;
    sm[t] = v; __syncthreads();
    int acc = v;
#pragma unroll
    for (int o = 1; o < 256; o <<= 1) {
        int add = (t >= o) ? sm[t - o] : 0;
        __syncthreads();
        acc += add; sm[t] = acc;
        __syncthreads();
    }
    int blockAgg = sm[255];
    if (t == 0) {
        volatile int* vstate = g_scan_state;
        volatile int* vagg   = g_scan_agg;
        volatile int* vinc   = g_scan_inc;
        if (b == 0) {
            vinc[0] = blockAgg;
            __threadfence();
            vstate[0] = 2;
            s_prefix = 0;
        } else {
            vagg[b] = blockAgg;
            __threadfence();
            vstate[b] = 1;
            int ex = 0, pb = b - 1;
            while (true) {
                int st;
                while ((st = vstate[pb]) == 0) { }
                if (st == 2) { ex += vinc[pb]; break; }
                ex += vagg[pb]; pb--;
            }
            vinc[b] = ex + blockAgg;
            __threadfence();
            vstate[b] = 2;
            s_prefix = ex;
        }
    }
    __syncthreads();
    int off = s_prefix;
    if (i < NN) {
        g_rowptr[i + 1] = off + acc;
        g_cur[i]        = off + acc - v;
    }
    if (i == 0) g_rowptr[0] = 0;
}

// ---------------- scatter edges into CSR (single 8B store per edge) ----------------
__global__ void scatter_edges(const int* __restrict__ ei, const float* __restrict__ w) {
    int e = blockIdx.x * blockDim.x + threadIdx.x;
    if (e >= EE) return;
    int d = parse_dst(ei, e);
    int pos = atomicAdd(&g_cur[d], 1);
    float wc = fminf(w[e], 4.f);
    float gate = fminf(fmaxf(1.f - 0.25f * wc, 0.f), 1.f);
    g_csr[pos] = make_int2(parse_src(ei, e), __float_as_int(gate));
}

// ---------------- fused residual MLP: relu(x@rW1+rb1)@rW2+rb2 -> g_xres ----------------
__global__ void gemm_res_fused(const float* __restrict__ X, const float* __restrict__ W1,
                               const float* __restrict__ B1, const float* __restrict__ W2,
                               const float* __restrict__ B2) {
    int warp = (blockIdx.x * blockDim.x + threadIdx.x) >> 5;
    int r0 = warp * 4;
    if (r0 >= NN) return;
    int lane = threadIdx.x & 31;
    float2 xa[4], t[4];
    float a0[4] = {0,0,0,0}, a1[4] = {0,0,0,0};
#pragma unroll
    for (int r = 0; r < 4; r++) xa[r] = ((const float2*)(X + (size_t)(r0 + r) * 64))[lane];
#pragma unroll
    for (int k = 0; k < 64; k += 2) {
        float2 w0 = ((const float2*)(W1 + k * 64))[lane];
        float2 w1 = ((const float2*)(W1 + (k + 1) * 64))[lane];
#pragma unroll
        for (int r = 0; r < 4; r++) {
            float x0 = __shfl_sync(0xffffffffu, xa[r].x, k >> 1);
            float x1 = __shfl_sync(0xffffffffu, xa[r].y, k >> 1);
            a0[r] += x0 * w0.x + x1 * w1.x;
            a1[r] += x0 * w0.y + x1 * w1.y;
        }
    }
    float bb0 = B1[2 * lane], bb1 = B1[2 * lane + 1];
#pragma unroll
    for (int r = 0; r < 4; r++) {
        t[r].x = fmaxf(a0[r] + bb0, 0.f);
        t[r].y = fmaxf(a1[r] + bb1, 0.f);
        a0[r] = 0.f; a1[r] = 0.f;
    }
#pragma unroll
    for (int k = 0; k < 64; k += 2) {
        float2 w0 = ((const float2*)(W2 + k * 64))[lane];
        float2 w1 = ((const float2*)(W2 + (k + 1) * 64))[lane];
#pragma unroll
        for (int r = 0; r < 4; r++) {
            float x0 = __shfl_sync(0xffffffffu, t[r].x, k >> 1);
            float x1 = __shfl_sync(0xffffffffu, t[r].y, k >> 1);
            a0[r] += x0 * w0.x + x1 * w1.x;
            a1[r] += x0 * w0.y + x1 * w1.y;
        }
    }
    float c0 = B2[2 * lane], c1 = B2[2 * lane + 1];
#pragma unroll
    for (int r = 0; r < 4; r++)
        ((float2*)(g_xres + (size_t)(r0 + r) * 64))[lane] = make_float2(a0[r] + c0, a1[r] + c1);
}

// ---------------- node prep: H=X@W (fp16 out), ad/as, xhat (fp16 out) ----------------
template <int LAYER>
__global__ void node_prep(const float* __restrict__ Xin, const float* __restrict__ W,
                          const float* __restrict__ att) {
    int warp = (blockIdx.x * blockDim.x + threadIdx.x) >> 5;
    int r0 = warp * 4;
    if (r0 >= NN) return;
    int lane = threadIdx.x & 31;
    const float* X = (LAYER == 0) ? Xin : g_h0;
    float2 xa[4];
    float a0[4] = {0,0,0,0}, a1[4] = {0,0,0,0};
#pragma unroll
    for (int r = 0; r < 4; r++) xa[r] = ((const float2*)(X + (size_t)(r0 + r) * 64))[lane];
#pragma unroll
    for (int k = 0; k < 64; k += 2) {
        float2 w0 = ((const float2*)(W + k * 64))[lane];
        float2 w1 = ((const float2*)(W + (k + 1) * 64))[lane];
#pragma unroll
        for (int r = 0; r < 4; r++) {
            float x0 = __shfl_sync(0xffffffffu, xa[r].x, k >> 1);
            float x1 = __shfl_sync(0xffffffffu, xa[r].y, k >> 1);
            a0[r] += x0 * w0.x + x1 * w1.x;
            a1[r] += x0 * w0.y + x1 * w1.y;
        }
    }
    float at0 = att[2 * lane], at1 = att[2 * lane + 1];
    float at2 = att[64 + 2 * lane], at3 = att[65 + 2 * lane];
#pragma unroll
    for (int r = 0; r < 4; r++) {
        ((__half2*)(g_Hh + (size_t)(r0 + r) * 64))[lane] = __floats2half2_rn(a0[r], a1[r]);
        float pa = a0[r] * at0 + a1[r] * at1;
        float pb = a0[r] * at2 + a1[r] * at3;
        float pn = xa[r].x * xa[r].x + xa[r].y * xa[r].y;
#pragma unroll
        for (int o = 16; o; o >>= 1) {
            pa += __shfl_xor_sync(0xffffffffu, pa, o);
            pb += __shfl_xor_sync(0xffffffffu, pb, o);
            pn += __shfl_xor_sync(0xffffffffu, pn, o);
        }
        float inv = 1.f / fmaxf(sqrtf(pn), 1e-8f);
        ((__half2*)(g_xh + (size_t)(r0 + r) * 64))[lane] =
            __floats2half2_rn(xa[r].x * inv, xa[r].y * inv);
        if (lane == 0) { g_ad[r0 + r] = pa; g_as[r0 + r] = pb; }
    }
}

// unpack 8 halves (loaded as float4) to 8 floats
__device__ __forceinline__ void h8_to_f8(float4 raw, float* f) {
    const __half2* h = (const __half2*)&raw;
#pragma unroll
    for (int i = 0; i < 4; i++) {
        float2 v = __half22float2(h[i]);
        f[2 * i] = v.x; f[2 * i + 1] = v.y;
    }
}

// ---------------- fused edge engine: warp per node, no smem (keep L1 for gathers) ----
// 8 lanes/edge, each lane covers 8 columns via one 16B fp16 load. Pipelined loops.
template <int LAYER>
__global__ void edge_fused(const float* __restrict__ beta, const float* __restrict__ B,
                           float* __restrict__ outp) {
    int n = (blockIdx.x * blockDim.x + threadIdx.x) >> 5;
    if (n >= NN) return;
    int lane = threadIdx.x & 31;
    int p = lane & 7;          // column-slot within 8-lane group (8 cols each)
    int grp = lane >> 3;       // edge group 0..3
    int esel = (lane * 8) & 31;

    float xq[8];
    h8_to_f8(((const float4*)(g_xh + (size_t)n * 64))[p], xq);
    float ad = g_ad[n];
    int beg = g_rowptr[n], end = g_rowptr[n + 1];
    float bb = 1.f / (1.f + __expf(-beta[0]));

    float sg = 0.f, sc = 0.f;

    // ---- pass A: dot + logit, raw exps, sums (pipelined) ----
    {
        int idx = beg + grp;
        int s = (idx < end) ? g_csr[idx].x : 0;
        float4 raw = ((const float4*)(g_xh + (size_t)s * 64))[p];
        for (int j0 = beg; j0 < end; j0 += 4) {
            int idxn = j0 + 4 + grp;
            int sn = (idxn < end) ? g_csr[idxn].x : 0;
            float4 rawn = ((const float4*)(g_xh + (size_t)sn * 64))[p];
            float q[8];
            h8_to_f8(raw, q);
            float d = 0.f;
#pragma unroll
            for (int i = 0; i < 8; i++) d += xq[i] * q[i];
            d += __shfl_xor_sync(0xffffffffu, d, 4, 8);
            d += __shfl_xor_sync(0xffffffffu, d, 2, 8);
            d += __shfl_xor_sync(0xffffffffu, d, 1, 8);
            float dsel = __shfl_sync(0xffffffffu, d, esel);
            int   ssel = __shfl_sync(0xffffffffu, s, esel);
            if (lane < min(4, end - j0)) {
                float lg = ad + g_as[ssel];
                lg = fmaxf(lg, 0.2f * lg);               // leaky relu
                float eg = __expf(lg);                   // no shift: |lg| small
                float ec = __expf(dsel);                 // cos in [-1,1]
                g_ec[j0 + lane] = make_float2(eg, ec);
                sg += eg; sc += ec;
            }
            s = sn; raw = rawn;
        }
    }
    sg += __shfl_xor_sync(0xffffffffu, sg, 1, 4);
    sg += __shfl_xor_sync(0xffffffffu, sg, 2, 4);
    sc += __shfl_xor_sync(0xffffffffu, sc, 1, 4);
    sc += __shfl_xor_sync(0xffffffffu, sc, 2, 4);
    sg = __shfl_sync(0xffffffffu, sg, 0);
    sc = __shfl_sync(0xffffffffu, sc, 0);
    float wg = (1.f - bb) / (sg + 1e-16f);
    float wc = bb / (sc + 1e-16f);

    // ---- pass C: fused alpha, gate, exp; unnormalized aggregate (pipelined) ----
    float acc[8] = {0,0,0,0,0,0,0,0};
    float st = 0.f;
    {
        int idx = beg + grp;
        int2 c = (idx < end) ? g_csr[idx] : make_int2(0, 0);
        float4 hraw = ((const float4*)(g_Hh + (size_t)c.x * 64))[p];
        int eidx = min(beg + lane, end - 1);
        float2 le = g_ec[eidx];
        for (int j0 = beg; j0 < end; j0 += 4) {
            int idxn = j0 + 4 + grp;
            int2 cn = (idxn < end) ? g_csr[idxn] : make_int2(0, 0);
            float4 hrawn = ((const float4*)(g_Hh + (size_t)cn.x * 64))[p];
            int eidxn = min(j0 + 4 + lane, end - 1);
            float2 len = g_ec[eidxn];

            // gate for edge i (lanes 0-3) comes from lane 8i's int2 load
            float gt = __shfl_sync(0xffffffffu, __int_as_float(c.y), esel);
            float et = 0.f;
            if (lane < min(4, end - j0)) {
                float tv = (le.x * wg + le.y * wc) * gt;   // in [0,1]
                et = __expf(tv);
                st += et;
            }
            float etg = __shfl_sync(0xffffffffu, et, grp);
            float h[8];
            h8_to_f8(hraw, h);
#pragma unroll
            for (int i = 0; i < 8; i++) acc[i] += etg * h[i];

            c = cn; hraw = hrawn; le = len;
        }
    }
    st += __shfl_xor_sync(0xffffffffu, st, 1, 4);
    st += __shfl_xor_sync(0xffffffffu, st, 2, 4);
    st  = __shfl_sync(0xffffffffu, st, 0);
#pragma unroll
    for (int i = 0; i < 8; i++) {
        acc[i] += __shfl_xor_sync(0xffffffffu, acc[i], 8);
        acc[i] += __shfl_xor_sync(0xffffffffu, acc[i], 16);
    }
    float inv = 1.f / (st + 1e-16f);
    if (lane < 8) {                                  // grp==0 lanes hold final cols 8p..8p+8
        float o[8];
#pragma unroll
        for (int i = 0; i < 8; i++) o[i] = acc[i] * inv + B[p * 8 + i];
        if (LAYER == 0) {
#pragma unroll
            for (int i = 0; i < 8; i++) o[i] = elu1(elu1(o[i]));
            float4* dst = (float4*)(g_h0 + (size_t)n * 64 + p * 8);
            dst[0] = make_float4(o[0], o[1], o[2], o[3]);
            dst[1] = make_float4(o[4], o[5], o[6], o[7]);
        } else {
            const float4* rr = (const float4*)(g_xres + (size_t)n * 64 + p * 8);
            float4 r0 = rr[0], r1 = rr[1];
            o[0] = elu1(o[0]) + r0.x; o[1] = elu1(o[1]) + r0.y;
            o[2] = elu1(o[2]) + r0.z; o[3] = elu1(o[3]) + r0.w;
            o[4] = elu1(o[4]) + r1.x; o[5] = elu1(o[5]) + r1.y;
            o[6] = elu1(o[6]) + r1.z; o[7] = elu1(o[7]) + r1.w;
            float4* dst = (float4*)(outp + (size_t)n * 64 + p * 8);
            dst[0] = make_float4(o[0], o[1], o[2], o[3]);
            dst[1] = make_float4(o[4], o[5], o[6], o[7]);
        }
    }
}

// ---------------- launch ----------------
extern "C" void kernel_launch(void* const* d_in, const int* in_sizes, int n_in,
                              void* d_out, int out_size) {
    const float* x     = (const float*)d_in[0];
    const int*   ei    = (const int*)d_in[1];
    const float* ea    = (const float*)d_in[2];
    const float* W0    = (const float*)d_in[3];
    const float* att0  = (const float*)d_in[4];
    const float* beta0 = (const float*)d_in[5];
    const float* b0    = (const float*)d_in[6];
    const float* W1    = (const float*)d_in[7];
    const float* att1  = (const float*)d_in[8];
    const float* beta1 = (const float*)d_in[9];
    const float* b1    = (const float*)d_in[10];
    const float* rW1   = (const float*)d_in[11];
    const float* rb1   = (const float*)d_in[12];
    const float* rW2   = (const float*)d_in[13];
    const float* rb2   = (const float*)d_in[14];
    float* out = (float*)d_out;

    const int EDGE_GRID  = EE / 256;                 // 5000
    const int PREP_GRID  = (NN / 4 + 7) / 8;         // 1563 (4 rows/warp, 8 warps/blk)
    const int EDGEF_GRID = NN / 8;                   // 6250 (warp per node)

    init_kernel<<<NBLK, 256>>>(ei);                  // 0
    edge_hist<<<EDGE_GRID, 256>>>(ei);               // 1
    scan_lookback<<<NBLK, 256>>>();                  // 2
    scatter_edges<<<EDGE_GRID, 256>>>(ei, ea);       // 3

    node_prep<0><<<PREP_GRID, 256>>>(x, W0, att0);   // 4
    edge_fused<0><<<EDGEF_GRID, 256>>>(beta0, b0, out); // 5  <- ncu window

    node_prep<1><<<PREP_GRID, 256>>>(x, W1, att1);   // 6
    gemm_res_fused<<<PREP_GRID, 256>>>(x, rW1, rb1, rW2, rb2); // 7
    edge_fused<1><<<EDGEF_GRID, 256>>>(beta1, b1, out);        // 8
}